// round 6
// baseline (speedup 1.0000x reference)
#include <cuda_runtime.h>
#include <stdint.h>

// SparseGather: out[m, i, j, c] = inputs[n_m, y0_m + i, x0_m + j, c]
// inputs: (N=4, H=512, W=512, C=64) fp32
// active_block_indices: (M=4096, 3) int32 -> (n, by, bx); y0 = by*16, x0 = bx*16
// out: (M, 16, 16, 64) fp32
//
// Units of float4 (C=64 -> 16 float4 per pixel):
//   C4   = 16
//   WC4  = 512 * 16 = 8192   (row stride, float4)
//   HWC4 = 512 * WC4         (image stride, float4)
//
// R6: eighth-block per CTA (2 rows), grid = 8*M = 32768, 256 threads.
//   Granularity gradient 16->8->4 rows gave DRAM% 75.3->76.1->76.9; this is
//   the last step (MLP_p1=2 puts oe*MLP_p1 at the ~16 spread threshold).
//   __ldcg reads (no L1 allocate; zero intra-SM reuse), __stcs stores
//   (evict-first: 268 MB write stream must not evict reusable input in L2).

#define C4   16
#define WC4  (512 * C4)
#define HWC4 (512 * WC4)

__global__ __launch_bounds__(256) void sparse_gather_kernel(
    const float4* __restrict__ in,
    const int*    __restrict__ idx,
    float4*       __restrict__ out)
{
    const int b  = blockIdx.x;     // 0 .. 8*M-1
    const int m  = b >> 3;         // block index
    const int r0 = (b & 7) << 1;   // row offset: 0,2,4,...,14
    const int t  = threadIdx.x;    // 0..255

    const int n  = idx[3 * m + 0];
    const int by = idx[3 * m + 1];
    const int bx = idx[3 * m + 2];

    const float4* src = in
        + (size_t)n * HWC4
        + (size_t)(by * 16 + r0) * WC4
        + (size_t)(bx * 16) * C4;

    float4* dst = out + (size_t)m * 4096 + (size_t)r0 * 256;

    // 2 rows; each row = 256 contiguous float4 on both sides.
    float4 v0 = __ldcg(&src[t]);
    float4 v1 = __ldcg(&src[WC4 + t]);
    __stcs(&dst[t],       v0);
    __stcs(&dst[256 + t], v1);
}

extern "C" void kernel_launch(void* const* d_in, const int* in_sizes, int n_in,
                              void* d_out, int out_size)
{
    const float4* in  = (const float4*)d_in[0];
    const int*    idx = (const int*)d_in[2];   // active_block_indices
    float4*       out = (float4*)d_out;

    const int M = in_sizes[2] / 3;             // 4096

    sparse_gather_kernel<<<8 * M, 256>>>(in, idx, out);
}